// round 1
// baseline (speedup 1.0000x reference)
#include <cuda_runtime.h>
#include <math.h>

#define BB 32
#define CTX 128
#define NF 128
#define NS 32768
#define NE 16
#define CH 256
#define WIN 512
#define NC 257
#define TC 514
#define NROWS (BB*NF)   // 4096

// ---------------- static scratch (no allocations allowed) ----------------
__device__ float g_base[BB*CH];
__device__ float g_act0[NROWS*CH];
__device__ float g_act1[NROWS*CH];
__device__ float g_xout[NROWS*TC];
__device__ float g_spec[NROWS*TC];
__device__ float g_basis[WIN*TC];
__device__ float g_frames[NROWS*WIN];
__device__ float g_sig[BB*NS];
__device__ int   g_evcnt[BB*NE];
__device__ int   g_evf[BB*NE*NF];
__device__ float g_eva[BB*NE*NF];

// ---------------- basis: irfft(512) + hann + 1/512 folded ----------------
// frames[t] = (1/512)*hann(t)*[ re0 + 2*sum_{k=1}^{255}(re_k cos - im_k sin) + re256*(-1)^t ]
// W[t, j]: j in [0,257) -> w_k*cos(2*pi*k*t/512)*hann/512 ; j in [257,514) -> -w_k*sin(...)*hann/512
__global__ void init_basis_k() {
    int idx = blockIdx.x*blockDim.x + threadIdx.x;
    if (idx >= WIN*TC) return;
    int t = idx / TC;
    int j = idx - t*TC;
    int k = (j < NC) ? j : (j - NC);
    int m = (k * t) & (WIN - 1);              // exact angle reduction
    float theta = (float)m * (float)(M_PI/256.0);
    float w = (k == 0 || k == NC-1) ? 1.f : 2.f;
    float hann = 0.5f*(1.f - cosf((float)t * (float)(M_PI/256.0)));
    float v = (j < NC) ? cosf(theta) : -sinf(theta);
    g_basis[idx] = v * w * hann * (1.f/512.f);
}

// ---------------- proj: base[b,c] = param[b,:] . proj_w[c,:] + proj_b[c] ----------------
__global__ void proj_k(const float* __restrict__ param, const float* __restrict__ proj_w,
                       const float* __restrict__ proj_b) {
    int b = blockIdx.x;
    int c = threadIdx.x;
    __shared__ float pr[CTX];
    if (c < CTX) pr[c] = param[b*CTX + c];
    __syncthreads();
    float acc = proj_b[c];
    const float* wr = proj_w + (size_t)c*CTX;
    #pragma unroll 8
    for (int k = 0; k < CTX; ++k) acc = fmaf(pr[k], wr[k], acc);
    g_base[b*CH + c] = acc;
}

// ---------------- act0[row,c] = base[b,c] + pos[f,c] ----------------
__global__ void addpos_k(const float* __restrict__ pos) {
    int idx = blockIdx.x*blockDim.x + threadIdx.x;
    if (idx >= NROWS*CH) return;
    int c = idx & (CH-1);
    int row = idx >> 8;
    int b = row >> 7;
    int f = row & (NF-1);
    g_act0[idx] = g_base[b*CH + c] + pos[f*CH + c];
}

// ---------------- tiled fp32 GEMM: C[M,N] = A[M,K] @ W[N,K]^T (+bias)(+leaky 0.2) ----------------
template<bool RELU, bool BIAS>
__global__ void __launch_bounds__(256) gemm_k(const float* __restrict__ A,
                                              const float* __restrict__ W,
                                              const float* __restrict__ bias,
                                              float* __restrict__ C,
                                              int M, int N, int K) {
    __shared__ float As[16][68];
    __shared__ float Ws[16][68];
    int tx = threadIdx.x, ty = threadIdx.y;
    int tid = ty*16 + tx;
    int row0 = blockIdx.y * 64;
    int col0 = blockIdx.x * 64;
    float acc[4][4];
    #pragma unroll
    for (int i = 0; i < 4; ++i)
        #pragma unroll
        for (int j = 0; j < 4; ++j) acc[i][j] = 0.f;

    int ktiles = (K + 15) >> 4;
    for (int kt = 0; kt < ktiles; ++kt) {
        int k0 = kt << 4;
        #pragma unroll
        for (int l = 0; l < 4; ++l) {
            int lin = tid + l*256;
            int m = lin >> 4;
            int k = lin & 15;
            int gk = k0 + k;
            As[k][m] = (gk < K) ? A[(size_t)(row0+m)*K + gk] : 0.f;
            int gn = col0 + m;
            Ws[k][m] = (gk < K && gn < N) ? W[(size_t)gn*K + gk] : 0.f;
        }
        __syncthreads();
        #pragma unroll
        for (int kk = 0; kk < 16; ++kk) {
            float4 a = *(const float4*)&As[kk][ty*4];
            float4 w = *(const float4*)&Ws[kk][tx*4];
            float av[4] = {a.x, a.y, a.z, a.w};
            float wv[4] = {w.x, w.y, w.z, w.w};
            #pragma unroll
            for (int i = 0; i < 4; ++i)
                #pragma unroll
                for (int j = 0; j < 4; ++j)
                    acc[i][j] = fmaf(av[i], wv[j], acc[i][j]);
        }
        __syncthreads();
    }
    #pragma unroll
    for (int i = 0; i < 4; ++i) {
        int r = row0 + ty*4 + i;
        #pragma unroll
        for (int j = 0; j < 4; ++j) {
            int c = col0 + tx*4 + j;
            if (c < N) {
                float v = acc[i][j];
                if (BIAS) v += bias[c];
                if (RELU) v = (v > 0.f) ? v : 0.2f*v;
                C[(size_t)r*N + c] = v;
            }
        }
    }
}

// ---------------- phase cumsum + complex exp -> spec (re | im) ----------------
__global__ void spec_k(const float* __restrict__ noise) {
    int b = blockIdx.x;
    int k = threadIdx.x;
    if (k >= NC) return;
    float freqpi = (float)k * (float)M_PI * (1.f/256.f);
    const float* xp  = g_xout + (size_t)b*NF*TC;
    const float* np0 = noise  + (size_t)b*NF*NC + k;
    float* sre = g_spec + (size_t)b*NF*TC + k;
    float p = 0.f;
    // software-pipelined: prefetch next frame while computing current
    float mg = xp[2*k], ph = xp[2*k+1], ns = np0[0];
    for (int f = 0; f < NF; ++f) {
        float mgc = mg, phc = ph, nsc = ns;
        if (f < NF-1) {
            const float* x2 = xp + (size_t)(f+1)*TC;
            mg = x2[2*k]; ph = x2[2*k+1];
            ns = np0[(size_t)(f+1)*NC];
        }
        p = fmaf(fmaf(phc, nsc, 1.f), freqpi, p);
        float s, c;
        sincosf(p, &s, &c);
        float mm = fabsf(mgc);
        sre[(size_t)f*TC]      = mm * c;
        sre[(size_t)f*TC + NC] = mm * s;
    }
}

// ---------------- overlap-add (hop=256 => exactly 2 taps per sample) ----------------
__global__ void sig_k() {
    int idx = blockIdx.x*blockDim.x + threadIdx.x;
    if (idx >= BB*NS) return;
    int b = idx >> 15;
    int s = idx & (NS-1);
    int f0 = s >> 8;
    int r = s & 255;
    float v = g_frames[((size_t)(b*NF + f0))*WIN + r];
    if (f0 > 0) v += g_frames[((size_t)(b*NF + f0 - 1))*WIN + r + 256];
    g_sig[idx] = v;
}

// ---------------- extract nonzeros of times (one-hot * amp, robust to any count) ----------------
__global__ void extract_k(const float* __restrict__ times) {
    int be = blockIdx.x*blockDim.x + threadIdx.x;
    if (be >= BB*NE) return;
    int cnt = 0;
    for (int f = 0; f < NF; ++f) {
        float v = times[(size_t)be*NF + f];
        if (v != 0.f) { g_evf[be*NF + cnt] = f; g_eva[be*NF + cnt] = v; ++cnt; }
    }
    g_evcnt[be] = cnt;
}

// ---------------- sparse shift-add convolution: out[b,e,t] = sum_j a_j * sig[b, t-256*f_j] ----------------
__global__ void conv_k(float* __restrict__ out) {
    int be = blockIdx.y;
    int b = be >> 4;
    int t = (blockIdx.x*blockDim.x + threadIdx.x) * 4;
    int cnt = g_evcnt[be];
    const float* sg = g_sig + (size_t)b*NS;
    float4 acc = make_float4(0.f, 0.f, 0.f, 0.f);
    for (int j = 0; j < cnt; ++j) {
        int f = g_evf[be*NF + j];
        float a = g_eva[be*NF + j];
        int s = t - (f << 8);           // multiple of 4 -> 16B aligned when >= 0
        if (s >= 0) {
            float4 v = *(const float4*)(sg + s);
            acc.x = fmaf(a, v.x, acc.x);
            acc.y = fmaf(a, v.y, acc.y);
            acc.z = fmaf(a, v.z, acc.z);
            acc.w = fmaf(a, v.w, acc.w);
        }
    }
    *(float4*)(out + (size_t)be*NS + t) = acc;
}

// ---------------- launch ----------------
extern "C" void kernel_launch(void* const* d_in, const int* in_sizes, int n_in,
                              void* d_out, int out_size) {
    const float* param  = (const float*)d_in[0];
    const float* times  = (const float*)d_in[1];
    const float* noise  = (const float*)d_in[2];
    const float* pos    = (const float*)d_in[3];
    const float* proj_w = (const float*)d_in[4];
    const float* proj_b = (const float*)d_in[5];
    const float* w0     = (const float*)d_in[6];
    const float* b0     = (const float*)d_in[7];
    const float* w1     = (const float*)d_in[8];
    const float* b1     = (const float*)d_in[9];
    const float* w2     = (const float*)d_in[10];
    const float* b2     = (const float*)d_in[11];
    const float* w_out  = (const float*)d_in[12];
    const float* b_out  = (const float*)d_in[13];
    float* out = (float*)d_out;

    float *act0, *act1, *xout, *spec, *basis, *frames;
    cudaGetSymbolAddress((void**)&act0,   g_act0);
    cudaGetSymbolAddress((void**)&act1,   g_act1);
    cudaGetSymbolAddress((void**)&xout,   g_xout);
    cudaGetSymbolAddress((void**)&spec,   g_spec);
    cudaGetSymbolAddress((void**)&basis,  g_basis);
    cudaGetSymbolAddress((void**)&frames, g_frames);

    dim3 tb(16, 16);

    init_basis_k<<<(WIN*TC + 255)/256, 256>>>();
    proj_k<<<BB, CH>>>(param, proj_w, proj_b);
    addpos_k<<<(NROWS*CH + 255)/256, 256>>>(pos);

    gemm_k<true,  true ><<<dim3(CH/64,   NROWS/64), tb>>>(act0, w0,    b0,    act1,   NROWS, CH,  CH);
    gemm_k<true,  true ><<<dim3(CH/64,   NROWS/64), tb>>>(act1, w1,    b1,    act0,   NROWS, CH,  CH);
    gemm_k<true,  true ><<<dim3(CH/64,   NROWS/64), tb>>>(act0, w2,    b2,    act1,   NROWS, CH,  CH);
    gemm_k<false, true ><<<dim3(9,       NROWS/64), tb>>>(act1, w_out, b_out, xout,   NROWS, TC,  CH);

    spec_k<<<BB, 288>>>(noise);

    gemm_k<false, false><<<dim3(WIN/64,  NROWS/64), tb>>>(spec, basis, (const float*)0, frames, NROWS, WIN, TC);

    sig_k<<<(BB*NS + 255)/256, 256>>>();
    extract_k<<<2, 256>>>(times);
    conv_k<<<dim3(NS/1024, BB*NE), 256>>>(out);
}

// round 2
// speedup vs baseline: 1.3582x; 1.3582x over previous
#include <cuda_runtime.h>
#include <math.h>

#define BB 32
#define CTX 128
#define NF 128
#define NS 32768
#define NE 16
#define CH 256
#define WIN 512
#define NC 257
#define TC 514
#define TCL 528              // padded leading dim for xout/spec/basis (16B aligned, 33 K-tiles of 16)
#define NROWS (BB*NF)        // 4096

// ---------------- static scratch (zero-initialized at module load; pads never written stay 0) ----------------
__device__ float g_base[BB*CH];
__device__ float g_act0[NROWS*CH];
__device__ float g_act1[NROWS*CH];
__device__ float g_xout[NROWS*TCL];
__device__ float g_spec[NROWS*TCL];   // cols [514,528) permanently zero
__device__ float g_basis[WIN*TCL];    // cols [514,528) written zero each launch
__device__ float g_frames[NROWS*WIN];
__device__ float g_sig[BB*NS];
__device__ float g_chsum[BB*4*NC];
__device__ int   g_evcnt[BB*NE];
__device__ int   g_evf[BB*NE*NF];
__device__ float g_eva[BB*NE*NF];

// ---------------- basis: irfft(512) + hann + 1/512 folded, padded to TCL cols ----------------
__global__ void init_basis_k() {
    int idx = blockIdx.x*blockDim.x + threadIdx.x;
    if (idx >= WIN*TCL) return;
    int t = idx / TCL;
    int j = idx - t*TCL;
    if (j >= TC) { g_basis[idx] = 0.f; return; }
    int k = (j < NC) ? j : (j - NC);
    int m = (k * t) & (WIN - 1);              // exact angle reduction
    float theta = (float)m * (float)(M_PI/256.0);
    float w = (k == 0 || k == NC-1) ? 1.f : 2.f;
    float hann = 0.5f*(1.f - cosf((float)t * (float)(M_PI/256.0)));
    float v = (j < NC) ? cosf(theta) : -sinf(theta);
    g_basis[idx] = v * w * hann * (1.f/512.f);
}

// ---------------- proj: base[b,c] = param[b,:] . proj_w[c,:] + proj_b[c] ----------------
__global__ void proj_k(const float* __restrict__ param, const float* __restrict__ proj_w,
                       const float* __restrict__ proj_b) {
    int b = blockIdx.x;
    int c = threadIdx.x;
    __shared__ float pr[CTX];
    if (c < CTX) pr[c] = param[b*CTX + c];
    __syncthreads();
    float acc = proj_b[c];
    const float* wr = proj_w + (size_t)c*CTX;
    #pragma unroll 8
    for (int k = 0; k < CTX; ++k) acc = fmaf(pr[k], wr[k], acc);
    g_base[b*CH + c] = acc;
}

// ---------------- GEMM: C[M,N] = A[M,K] @ W[N,K]^T (+bias)(+leaky 0.2) ----------------
// BM=128, BN=64, BK=16; 256 threads; 8x4 micro-tile; double-buffered smem.
// Requires: K % 16 == 0, M % 128 == 0, lda/ldw/ldc multiples of 4, row pointers 16B aligned.
// FUSEPOS: A[row,k] = base[row>>7, k] + pos[row&127, k]  (row0 % 128 == 0 so block spans one b)
template<bool RELU, bool BIAS, bool FUSEPOS>
__global__ void __launch_bounds__(256) gemm2_k(const float* __restrict__ A,
                                               const float* __restrict__ W,
                                               const float* __restrict__ bias,
                                               const float* __restrict__ base,
                                               const float* __restrict__ pos,
                                               float* __restrict__ C,
                                               int M, int N, int K,
                                               int lda, int ldw, int ldc) {
    __shared__ float As[2][16][132];
    __shared__ float Ws[2][16][68];
    int tid = threadIdx.x;
    int tx = tid & 15;          // N dir: 4 cols
    int ty = tid >> 4;          // M dir: 8 rows
    int row0 = blockIdx.y * 128;
    int col0 = blockIdx.x * 64;

    int am  = tid >> 2;         // 0..63 (A rows, +64 for second half)
    int akq = (tid & 3) << 2;   // 0,4,8,12 within K-tile
    int wn  = tid >> 2;         // 0..63 (W rows)

    auto loadTile = [&](int kt, float4& v0, float4& v1, float4& w) {
        int gk = kt*16 + akq;
        if (FUSEPOS) {
            float4 vb = *(const float4*)(base + (size_t)(row0 >> 7)*CH + gk);
            float4 p0 = *(const float4*)(pos + (size_t)am*CH + gk);
            float4 p1 = *(const float4*)(pos + (size_t)(am+64)*CH + gk);
            v0 = make_float4(vb.x+p0.x, vb.y+p0.y, vb.z+p0.z, vb.w+p0.w);
            v1 = make_float4(vb.x+p1.x, vb.y+p1.y, vb.z+p1.z, vb.w+p1.w);
        } else {
            v0 = *(const float4*)(A + (size_t)(row0+am)*lda + gk);
            v1 = *(const float4*)(A + (size_t)(row0+am+64)*lda + gk);
        }
        int gn = col0 + wn;
        if (gn < N) w = *(const float4*)(W + (size_t)gn*ldw + gk);
        else        w = make_float4(0.f, 0.f, 0.f, 0.f);
    };

    float4 pa0, pa1, pw;
    loadTile(0, pa0, pa1, pw);
    {
        As[0][akq+0][am] = pa0.x; As[0][akq+1][am] = pa0.y;
        As[0][akq+2][am] = pa0.z; As[0][akq+3][am] = pa0.w;
        As[0][akq+0][am+64] = pa1.x; As[0][akq+1][am+64] = pa1.y;
        As[0][akq+2][am+64] = pa1.z; As[0][akq+3][am+64] = pa1.w;
        Ws[0][akq+0][wn] = pw.x; Ws[0][akq+1][wn] = pw.y;
        Ws[0][akq+2][wn] = pw.z; Ws[0][akq+3][wn] = pw.w;
    }
    __syncthreads();

    float acc[8][4];
    #pragma unroll
    for (int i = 0; i < 8; ++i)
        #pragma unroll
        for (int j = 0; j < 4; ++j) acc[i][j] = 0.f;

    int ktiles = K >> 4;
    int buf = 0;
    for (int kt = 0; kt < ktiles; ++kt) {
        bool nxt = (kt + 1 < ktiles);
        if (nxt) loadTile(kt+1, pa0, pa1, pw);
        #pragma unroll
        for (int kk = 0; kk < 16; ++kk) {
            float4 a0 = *(const float4*)&As[buf][kk][ty*8];
            float4 a1 = *(const float4*)&As[buf][kk][ty*8+4];
            float4 bv = *(const float4*)&Ws[buf][kk][tx*4];
            float av[8] = {a0.x,a0.y,a0.z,a0.w,a1.x,a1.y,a1.z,a1.w};
            float wv[4] = {bv.x,bv.y,bv.z,bv.w};
            #pragma unroll
            for (int i = 0; i < 8; ++i)
                #pragma unroll
                for (int j = 0; j < 4; ++j)
                    acc[i][j] = fmaf(av[i], wv[j], acc[i][j]);
        }
        if (nxt) {
            int b1 = buf ^ 1;
            As[b1][akq+0][am] = pa0.x; As[b1][akq+1][am] = pa0.y;
            As[b1][akq+2][am] = pa0.z; As[b1][akq+3][am] = pa0.w;
            As[b1][akq+0][am+64] = pa1.x; As[b1][akq+1][am+64] = pa1.y;
            As[b1][akq+2][am+64] = pa1.z; As[b1][akq+3][am+64] = pa1.w;
            Ws[b1][akq+0][wn] = pw.x; Ws[b1][akq+1][wn] = pw.y;
            Ws[b1][akq+2][wn] = pw.z; Ws[b1][akq+3][wn] = pw.w;
        }
        __syncthreads();
        buf ^= 1;
    }

    float bz[4];
    #pragma unroll
    for (int j = 0; j < 4; ++j) {
        int c = col0 + tx*4 + j;
        bz[j] = (BIAS && c < N) ? bias[c] : 0.f;
    }
    bool fullcol = (col0 + tx*4 + 3 < N);
    #pragma unroll
    for (int i = 0; i < 8; ++i) {
        int r = row0 + ty*8 + i;
        float v[4];
        #pragma unroll
        for (int j = 0; j < 4; ++j) {
            float x = acc[i][j] + bz[j];
            if (RELU) x = (x > 0.f) ? x : 0.2f*x;
            v[j] = x;
        }
        float* cr = C + (size_t)r*ldc + col0 + tx*4;
        if (fullcol) {
            *(float4*)cr = make_float4(v[0], v[1], v[2], v[3]);
        } else {
            #pragma unroll
            for (int j = 0; j < 4; ++j)
                if (col0 + tx*4 + j < N) cr[j] = v[j];
        }
    }
}

// ---------------- phase cumsum (2-phase chunked) + complex exp -> spec ----------------
// chunk = 32 frames; thread handles one (b, chunk, k)
__global__ void spec_pre_k(const float* __restrict__ noise) {
    int idx = blockIdx.x*blockDim.x + threadIdx.x;
    if (idx >= BB*4*NC) return;
    int k = idx % NC;
    int r = idx / NC;          // b*4 + chunk
    int chunk = r & 3;
    int b = r >> 2;
    float freqpi = (float)k * (float)(M_PI/256.0);
    const float* xp = g_xout + (size_t)b*NF*TCL + (size_t)chunk*32*TCL + 2*k + 1;
    const float* np = noise  + (size_t)b*NF*NC + (size_t)chunk*32*NC + k;
    float s = 0.f;
    #pragma unroll 4
    for (int f = 0; f < 32; ++f)
        s = fmaf(fmaf(xp[(size_t)f*TCL], np[(size_t)f*NC], 1.f), freqpi, s);
    g_chsum[idx] = s;
}

__global__ void spec_main_k(const float* __restrict__ noise) {
    int idx = blockIdx.x*blockDim.x + threadIdx.x;
    if (idx >= BB*4*NC) return;
    int k = idx % NC;
    int r = idx / NC;
    int chunk = r & 3;
    int b = r >> 2;
    float freqpi = (float)k * (float)(M_PI/256.0);
    float p = 0.f;
    for (int c = 0; c < chunk; ++c)
        p += g_chsum[(b*4 + c)*NC + k];
    const float* xp = g_xout + (size_t)b*NF*TCL + (size_t)chunk*32*TCL + 2*k;
    const float* np = noise  + (size_t)b*NF*NC + (size_t)chunk*32*NC + k;
    float* sp = g_spec + (size_t)b*NF*TCL + (size_t)chunk*32*TCL + k;
    for (int f = 0; f < 32; ++f) {
        float mg = fabsf(xp[(size_t)f*TCL]);
        float ph = xp[(size_t)f*TCL + 1];
        float ns = np[(size_t)f*NC];
        p = fmaf(fmaf(ph, ns, 1.f), freqpi, p);
        float s, c;
        sincosf(p, &s, &c);
        sp[(size_t)f*TCL]      = mg * c;
        sp[(size_t)f*TCL + NC] = mg * s;
    }
}

// ---------------- overlap-add (hop=256 => exactly 2 taps per sample) ----------------
__global__ void sig_k() {
    int idx = blockIdx.x*blockDim.x + threadIdx.x;
    if (idx >= BB*NS) return;
    int b = idx >> 15;
    int s = idx & (NS-1);
    int f0 = s >> 8;
    int r = s & 255;
    float v = g_frames[((size_t)(b*NF + f0))*WIN + r];
    if (f0 > 0) v += g_frames[((size_t)(b*NF + f0 - 1))*WIN + r + 256];
    g_sig[idx] = v;
}

// ---------------- extract nonzeros of times ----------------
__global__ void extract_k(const float* __restrict__ times) {
    int be = blockIdx.x*blockDim.x + threadIdx.x;
    if (be >= BB*NE) return;
    int cnt = 0;
    for (int f = 0; f < NF; ++f) {
        float v = times[(size_t)be*NF + f];
        if (v != 0.f) { g_evf[be*NF + cnt] = f; g_eva[be*NF + cnt] = v; ++cnt; }
    }
    g_evcnt[be] = cnt;
}

// ---------------- sparse shift-add convolution ----------------
__global__ void conv_k(float* __restrict__ out) {
    int be = blockIdx.y;
    int b = be >> 4;
    int t = (blockIdx.x*blockDim.x + threadIdx.x) * 4;
    int cnt = g_evcnt[be];
    const float* sg = g_sig + (size_t)b*NS;
    float4 acc = make_float4(0.f, 0.f, 0.f, 0.f);
    for (int j = 0; j < cnt; ++j) {
        int f = g_evf[be*NF + j];
        float a = g_eva[be*NF + j];
        int s = t - (f << 8);
        if (s >= 0) {
            float4 v = *(const float4*)(sg + s);
            acc.x = fmaf(a, v.x, acc.x);
            acc.y = fmaf(a, v.y, acc.y);
            acc.z = fmaf(a, v.z, acc.z);
            acc.w = fmaf(a, v.w, acc.w);
        }
    }
    *(float4*)(out + (size_t)be*NS + t) = acc;
}

// ---------------- launch ----------------
extern "C" void kernel_launch(void* const* d_in, const int* in_sizes, int n_in,
                              void* d_out, int out_size) {
    const float* param  = (const float*)d_in[0];
    const float* times  = (const float*)d_in[1];
    const float* noise  = (const float*)d_in[2];
    const float* pos    = (const float*)d_in[3];
    const float* proj_w = (const float*)d_in[4];
    const float* proj_b = (const float*)d_in[5];
    const float* w0     = (const float*)d_in[6];
    const float* b0     = (const float*)d_in[7];
    const float* w1     = (const float*)d_in[8];
    const float* b1     = (const float*)d_in[9];
    const float* w2     = (const float*)d_in[10];
    const float* b2     = (const float*)d_in[11];
    const float* w_out  = (const float*)d_in[12];
    const float* b_out  = (const float*)d_in[13];
    float* out = (float*)d_out;

    float *base, *act0, *act1, *xout, *spec, *basis, *frames;
    cudaGetSymbolAddress((void**)&base,   g_base);
    cudaGetSymbolAddress((void**)&act0,   g_act0);
    cudaGetSymbolAddress((void**)&act1,   g_act1);
    cudaGetSymbolAddress((void**)&xout,   g_xout);
    cudaGetSymbolAddress((void**)&spec,   g_spec);
    cudaGetSymbolAddress((void**)&basis,  g_basis);
    cudaGetSymbolAddress((void**)&frames, g_frames);

    init_basis_k<<<(WIN*TCL + 255)/256, 256>>>();
    proj_k<<<BB, CH>>>(param, proj_w, proj_b);

    // layer0: A fused (base + pos)
    gemm2_k<true, true, true ><<<dim3(4, 32), 256>>>(
        (const float*)0, w0, b0, base, pos, act1, NROWS, CH, CH, CH, CH, CH);
    gemm2_k<true, true, false><<<dim3(4, 32), 256>>>(
        act1, w1, b1, (const float*)0, (const float*)0, act0, NROWS, CH, CH, CH, CH, CH);
    gemm2_k<true, true, false><<<dim3(4, 32), 256>>>(
        act0, w2, b2, (const float*)0, (const float*)0, act1, NROWS, CH, CH, CH, CH, CH);
    // out layer: N=514, C stride padded to 528
    gemm2_k<false, true, false><<<dim3(9, 32), 256>>>(
        act1, w_out, b_out, (const float*)0, (const float*)0, xout, NROWS, TC, CH, CH, CH, TCL);

    spec_pre_k <<<(BB*4*NC + 255)/256, 256>>>(noise);
    spec_main_k<<<(BB*4*NC + 255)/256, 256>>>(noise);

    // frames = spec[4096,528] @ basis[512,528]^T  (pads are zero)
    gemm2_k<false, false, false><<<dim3(8, 32), 256>>>(
        spec, basis, (const float*)0, (const float*)0, (const float*)0, frames,
        NROWS, WIN, TCL, TCL, TCL, WIN);

    sig_k<<<(BB*NS + 255)/256, 256>>>();
    extract_k<<<2, 256>>>(times);
    conv_k<<<dim3(NS/1024, BB*NE), 256>>>(out);
}

// round 4
// speedup vs baseline: 1.6837x; 1.2396x over previous
#include <cuda_runtime.h>
#include <cuda_bf16.h>
#include <math.h>

#define BB 32
#define CTX 128
#define NF 128
#define NS 32768
#define NE 16
#define CH 256
#define WIN 512
#define NC 257
#define TC 514
#define TCL 544              // padded leading dim (multiple of 32 for BK=32; 17 K-tiles)
#define NROWS (BB*NF)        // 4096

// ---------------- static scratch (zero-initialized at module load; pads stay 0) ----------------
__device__ float g_base[BB*CH];
__device__ float g_act0[NROWS*CH];
__device__ float g_act1[NROWS*CH];
__device__ float g_xout[NROWS*TCL];
__device__ float g_spec[NROWS*TCL];   // cols [514,544) never written -> stay 0 (deterministic)
__device__ float g_basis[WIN*TCL];    // cols [514,544) written 0 every launch
__device__ float g_frames[NROWS*WIN];
__device__ float g_sig[BB*NS];
__device__ float g_chsum[BB*4*NC];
__device__ int   g_evcnt[BB*NE];
__device__ int   g_evf[BB*NE*NF];
__device__ float g_eva[BB*NE*NF];

// ---------------- bf16 split helpers ----------------
__device__ __forceinline__ unsigned pack_bf2(float x, float y) {
    __nv_bfloat162 t = __floats2bfloat162_rn(x, y);
    return *reinterpret_cast<unsigned*>(&t);
}
__device__ __forceinline__ float bfres(float x) {
    return x - __bfloat162float(__float2bfloat16(x));
}

#define MMA_BF16(d, a, b) \
    asm volatile("mma.sync.aligned.m16n8k16.row.col.f32.bf16.bf16.f32 " \
                 "{%0,%1,%2,%3},{%4,%5,%6,%7},{%8,%9},{%0,%1,%2,%3};" \
                 : "+f"(d[0]), "+f"(d[1]), "+f"(d[2]), "+f"(d[3]) \
                 : "r"(a[0]), "r"(a[1]), "r"(a[2]), "r"(a[3]), "r"(b[0]), "r"(b[1]))

// ---------------- basis: irfft(512) + hann + 1/512 folded, padded to TCL cols ----------------
__global__ void init_basis_k() {
    int idx = blockIdx.x*blockDim.x + threadIdx.x;
    if (idx >= WIN*TCL) return;
    int t = idx / TCL;
    int j = idx - t*TCL;
    if (j >= TC) { g_basis[idx] = 0.f; return; }
    int k = (j < NC) ? j : (j - NC);
    int m = (k * t) & (WIN - 1);              // exact angle reduction
    float theta = (float)m * (float)(M_PI/256.0);
    float w = (k == 0 || k == NC-1) ? 1.f : 2.f;
    float hann = 0.5f*(1.f - cosf((float)t * (float)(M_PI/256.0)));
    float v = (j < NC) ? cosf(theta) : -sinf(theta);
    g_basis[idx] = v * w * hann * (1.f/512.f);
}

// ---------------- proj: base[b,c] = param[b,:] . proj_w[c,:] + proj_b[c] ----------------
__global__ void proj_k(const float* __restrict__ param, const float* __restrict__ proj_w,
                       const float* __restrict__ proj_b) {
    int b = blockIdx.x;
    int c = threadIdx.x;
    __shared__ float pr[CTX];
    if (c < CTX) pr[c] = param[b*CTX + c];
    __syncthreads();
    float acc = proj_b[c];
    const float* wr = proj_w + (size_t)c*CTX;
    #pragma unroll 8
    for (int k = 0; k < CTX; ++k) acc = fmaf(pr[k], wr[k], acc);
    g_base[b*CH + c] = acc;
}

// ---------------- tensor-core GEMM: C[M,N] = A[M,K] @ W[N,K]^T (+bias)(+leaky 0.2) ----------------
// bf16-split (hi+lo) mma.sync, fp32-grade precision (drops lo*lo, ~2^-17 rel).
// BM=128, BN=64, BK=32; 256 threads = 8 warps at 32x32 warp tiles.
// Requires K % 32 == 0, M % 128 == 0. FUSEPOS: A[row,k] = base[row>>7,k] + pos[row&127,k].
template<bool RELU, bool BIAS, bool FUSEPOS>
__global__ void __launch_bounds__(256) gemm3_k(const float* __restrict__ A,
                                               const float* __restrict__ W,
                                               const float* __restrict__ bias,
                                               const float* __restrict__ base,
                                               const float* __restrict__ pos,
                                               float* __restrict__ C,
                                               int M, int N, int K,
                                               int lda, int ldw, int ldc) {
    __shared__ __align__(16) __nv_bfloat16 Ahi[128][40];
    __shared__ __align__(16) __nv_bfloat16 Alo[128][40];
    __shared__ __align__(16) __nv_bfloat16 Bhi[64][40];
    __shared__ __align__(16) __nv_bfloat16 Blo[64][40];

    int tid = threadIdx.x;
    int row0 = blockIdx.y * 128;
    int col0 = blockIdx.x * 64;

    // loader mapping
    int arow = tid >> 1;            // 0..127
    int ac   = (tid & 1) << 4;      // 0 or 16 (element offset within K-tile)
    int brow = tid >> 1;            // 0..63 (tid < 128)
    int bc   = (tid & 1) << 4;

    // warp mapping: 4 (m) x 2 (n) warps; 32x32 warp tile
    int wid = tid >> 5;
    int lane = tid & 31;
    int wm0 = (wid >> 1) * 32;
    int wn0 = (wid & 1) * 32;
    int g = lane >> 2;              // 0..7
    int t = lane & 3;               // 0..3

    float4 ra[4];
    float4 rb[4];

    auto loadRegs = [&](int kt) {
        int gk = kt*32 + ac;
        if (FUSEPOS) {
            const float* bp = base + (size_t)(row0 >> 7)*CH + gk;
            const float* pp = pos  + (size_t)arow*CH + gk;
            #pragma unroll
            for (int q = 0; q < 4; ++q) {
                float4 vb = *(const float4*)(bp + q*4);
                float4 vp = *(const float4*)(pp + q*4);
                ra[q] = make_float4(vb.x+vp.x, vb.y+vp.y, vb.z+vp.z, vb.w+vp.w);
            }
        } else {
            const float* ap = A + (size_t)(row0 + arow)*lda + gk;
            #pragma unroll
            for (int q = 0; q < 4; ++q) ra[q] = *(const float4*)(ap + q*4);
        }
        if (tid < 128) {
            int gn = col0 + brow;
            if (gn < N) {
                const float* wp = W + (size_t)gn*ldw + kt*32 + bc;
                #pragma unroll
                for (int q = 0; q < 4; ++q) rb[q] = *(const float4*)(wp + q*4);
            } else {
                #pragma unroll
                for (int q = 0; q < 4; ++q) rb[q] = make_float4(0.f,0.f,0.f,0.f);
            }
        }
    };

    auto storeSmem = [&]() {
        unsigned h[8], l[8];
        #pragma unroll
        for (int q = 0; q < 4; ++q) {
            float4 v = ra[q];
            h[2*q]   = pack_bf2(v.x, v.y);
            h[2*q+1] = pack_bf2(v.z, v.w);
            l[2*q]   = pack_bf2(bfres(v.x), bfres(v.y));
            l[2*q+1] = pack_bf2(bfres(v.z), bfres(v.w));
        }
        *(uint4*)&Ahi[arow][ac]   = make_uint4(h[0],h[1],h[2],h[3]);
        *(uint4*)&Ahi[arow][ac+8] = make_uint4(h[4],h[5],h[6],h[7]);
        *(uint4*)&Alo[arow][ac]   = make_uint4(l[0],l[1],l[2],l[3]);
        *(uint4*)&Alo[arow][ac+8] = make_uint4(l[4],l[5],l[6],l[7]);
        if (tid < 128) {
            #pragma unroll
            for (int q = 0; q < 4; ++q) {
                float4 v = rb[q];
                h[2*q]   = pack_bf2(v.x, v.y);
                h[2*q+1] = pack_bf2(v.z, v.w);
                l[2*q]   = pack_bf2(bfres(v.x), bfres(v.y));
                l[2*q+1] = pack_bf2(bfres(v.z), bfres(v.w));
            }
            *(uint4*)&Bhi[brow][bc]   = make_uint4(h[0],h[1],h[2],h[3]);
            *(uint4*)&Bhi[brow][bc+8] = make_uint4(h[4],h[5],h[6],h[7]);
            *(uint4*)&Blo[brow][bc]   = make_uint4(l[0],l[1],l[2],l[3]);
            *(uint4*)&Blo[brow][bc+8] = make_uint4(l[4],l[5],l[6],l[7]);
        }
    };

    float acc[2][4][4];
    #pragma unroll
    for (int mt = 0; mt < 2; ++mt)
        #pragma unroll
        for (int nt = 0; nt < 4; ++nt)
            #pragma unroll
            for (int i = 0; i < 4; ++i) acc[mt][nt][i] = 0.f;

    int ktiles = K >> 5;
    loadRegs(0);
    for (int kt = 0; kt < ktiles; ++kt) {
        __syncthreads();            // previous tile fully consumed
        storeSmem();
        __syncthreads();            // smem ready
        if (kt + 1 < ktiles) loadRegs(kt + 1);    // overlap gmem with mma

        #pragma unroll
        for (int kk = 0; kk < 32; kk += 16) {
            unsigned ah[2][4], al[2][4], bh[4][2], bl[4][2];
            #pragma unroll
            for (int mt = 0; mt < 2; ++mt) {
                int r = wm0 + mt*16;
                ah[mt][0] = *(unsigned*)&Ahi[r+g   ][kk+2*t];
                ah[mt][1] = *(unsigned*)&Ahi[r+8+g ][kk+2*t];
                ah[mt][2] = *(unsigned*)&Ahi[r+g   ][kk+8+2*t];
                ah[mt][3] = *(unsigned*)&Ahi[r+8+g ][kk+8+2*t];
                al[mt][0] = *(unsigned*)&Alo[r+g   ][kk+2*t];
                al[mt][1] = *(unsigned*)&Alo[r+8+g ][kk+2*t];
                al[mt][2] = *(unsigned*)&Alo[r+g   ][kk+8+2*t];
                al[mt][3] = *(unsigned*)&Alo[r+8+g ][kk+8+2*t];
            }
            #pragma unroll
            for (int nt = 0; nt < 4; ++nt) {
                int n = wn0 + nt*8 + g;
                bh[nt][0] = *(unsigned*)&Bhi[n][kk+2*t];
                bh[nt][1] = *(unsigned*)&Bhi[n][kk+8+2*t];
                bl[nt][0] = *(unsigned*)&Blo[n][kk+2*t];
                bl[nt][1] = *(unsigned*)&Blo[n][kk+8+2*t];
            }
            #pragma unroll
            for (int mt = 0; mt < 2; ++mt)
                #pragma unroll
                for (int nt = 0; nt < 4; ++nt) {
                    MMA_BF16(acc[mt][nt], ah[mt], bh[nt]);
                    MMA_BF16(acc[mt][nt], ah[mt], bl[nt]);
                    MMA_BF16(acc[mt][nt], al[mt], bh[nt]);
                }
        }
    }

    // epilogue: thread owns (r = row0+wm0+mt*16+g(+8), c = col0+wn0+nt*8+2t(+1))
    #pragma unroll
    for (int nt = 0; nt < 4; ++nt) {
        int c = col0 + wn0 + nt*8 + 2*t;
        if (c >= N) continue;       // N even; pairs never straddle
        float b0 = BIAS ? bias[c]   : 0.f;
        float b1 = BIAS ? bias[c+1] : 0.f;
        #pragma unroll
        for (int mt = 0; mt < 2; ++mt) {
            int r0 = row0 + wm0 + mt*16 + g;
            float v0 = acc[mt][nt][0] + b0;
            float v1 = acc[mt][nt][1] + b1;
            float v2 = acc[mt][nt][2] + b0;
            float v3 = acc[mt][nt][3] + b1;
            if (RELU) {
                v0 = (v0 > 0.f) ? v0 : 0.2f*v0;
                v1 = (v1 > 0.f) ? v1 : 0.2f*v1;
                v2 = (v2 > 0.f) ? v2 : 0.2f*v2;
                v3 = (v3 > 0.f) ? v3 : 0.2f*v3;
            }
            *(float2*)(C + (size_t)r0*ldc + c)     = make_float2(v0, v1);
            *(float2*)(C + (size_t)(r0+8)*ldc + c) = make_float2(v2, v3);
        }
    }
}

// ---------------- phase cumsum (2-phase chunked) + complex exp -> spec ----------------
__global__ void spec_pre_k(const float* __restrict__ noise) {
    int idx = blockIdx.x*blockDim.x + threadIdx.x;
    if (idx >= BB*4*NC) return;
    int k = idx % NC;
    int r = idx / NC;          // b*4 + chunk
    int chunk = r & 3;
    int b = r >> 2;
    float freqpi = (float)k * (float)(M_PI/256.0);
    const float* xp = g_xout + (size_t)b*NF*TCL + (size_t)chunk*32*TCL + 2*k + 1;
    const float* np = noise  + (size_t)b*NF*NC + (size_t)chunk*32*NC + k;
    float s = 0.f;
    #pragma unroll 4
    for (int f = 0; f < 32; ++f)
        s = fmaf(fmaf(xp[(size_t)f*TCL], np[(size_t)f*NC], 1.f), freqpi, s);
    g_chsum[idx] = s;
}

__global__ void spec_main_k(const float* __restrict__ noise) {
    int idx = blockIdx.x*blockDim.x + threadIdx.x;
    if (idx >= BB*4*NC) return;
    int k = idx % NC;
    int r = idx / NC;
    int chunk = r & 3;
    int b = r >> 2;
    float freqpi = (float)k * (float)(M_PI/256.0);
    float p = 0.f;
    for (int c = 0; c < chunk; ++c)
        p += g_chsum[(b*4 + c)*NC + k];
    const float* xp = g_xout + (size_t)b*NF*TCL + (size_t)chunk*32*TCL + 2*k;
    const float* np = noise  + (size_t)b*NF*NC + (size_t)chunk*32*NC + k;
    float* sp = g_spec + (size_t)b*NF*TCL + (size_t)chunk*32*TCL + k;
    for (int f = 0; f < 32; ++f) {
        float mg = fabsf(xp[(size_t)f*TCL]);
        float ph = xp[(size_t)f*TCL + 1];
        float ns = np[(size_t)f*NC];
        p = fmaf(fmaf(ph, ns, 1.f), freqpi, p);
        float s, c;
        sincosf(p, &s, &c);
        sp[(size_t)f*TCL]      = mg * c;
        sp[(size_t)f*TCL + NC] = mg * s;
    }
}

// ---------------- overlap-add (hop=256 => exactly 2 taps per sample) ----------------
__global__ void sig_k() {
    int idx = blockIdx.x*blockDim.x + threadIdx.x;
    if (idx >= BB*NS) return;
    int b = idx >> 15;
    int s = idx & (NS-1);
    int f0 = s >> 8;
    int r = s & 255;
    float v = g_frames[((size_t)(b*NF + f0))*WIN + r];
    if (f0 > 0) v += g_frames[((size_t)(b*NF + f0 - 1))*WIN + r + 256];
    g_sig[idx] = v;
}

// ---------------- extract nonzeros of times ----------------
__global__ void extract_k(const float* __restrict__ times) {
    int be = blockIdx.x*blockDim.x + threadIdx.x;
    if (be >= BB*NE) return;
    int cnt = 0;
    for (int f = 0; f < NF; ++f) {
        float v = times[(size_t)be*NF + f];
        if (v != 0.f) { g_evf[be*NF + cnt] = f; g_eva[be*NF + cnt] = v; ++cnt; }
    }
    g_evcnt[be] = cnt;
}

// ---------------- sparse shift-add convolution ----------------
__global__ void conv_k(float* __restrict__ out) {
    int be = blockIdx.y;
    int b = be >> 4;
    int t = (blockIdx.x*blockDim.x + threadIdx.x) * 4;
    int cnt = g_evcnt[be];
    const float* sg = g_sig + (size_t)b*NS;
    float4 acc = make_float4(0.f, 0.f, 0.f, 0.f);
    for (int j = 0; j < cnt; ++j) {
        int f = g_evf[be*NF + j];
        float a = g_eva[be*NF + j];
        int s = t - (f << 8);
        if (s >= 0) {
            float4 v = *(const float4*)(sg + s);
            acc.x = fmaf(a, v.x, acc.x);
            acc.y = fmaf(a, v.y, acc.y);
            acc.z = fmaf(a, v.z, acc.z);
            acc.w = fmaf(a, v.w, acc.w);
        }
    }
    *(float4*)(out + (size_t)be*NS + t) = acc;
}

// ---------------- launch ----------------
extern "C" void kernel_launch(void* const* d_in, const int* in_sizes, int n_in,
                              void* d_out, int out_size) {
    const float* param  = (const float*)d_in[0];
    const float* times  = (const float*)d_in[1];
    const float* noise  = (const float*)d_in[2];
    const float* pos    = (const float*)d_in[3];
    const float* proj_w = (const float*)d_in[4];
    const float* proj_b = (const float*)d_in[5];
    const float* w0     = (const float*)d_in[6];
    const float* b0     = (const float*)d_in[7];
    const float* w1     = (const float*)d_in[8];
    const float* b1     = (const float*)d_in[9];
    const float* w2     = (const float*)d_in[10];
    const float* b2     = (const float*)d_in[11];
    const float* w_out  = (const float*)d_in[12];
    const float* b_out  = (const float*)d_in[13];
    float* out = (float*)d_out;

    float *base, *act0, *act1, *xout, *spec, *basis, *frames;
    cudaGetSymbolAddress((void**)&base,   g_base);
    cudaGetSymbolAddress((void**)&act0,   g_act0);
    cudaGetSymbolAddress((void**)&act1,   g_act1);
    cudaGetSymbolAddress((void**)&xout,   g_xout);
    cudaGetSymbolAddress((void**)&spec,   g_spec);
    cudaGetSymbolAddress((void**)&basis,  g_basis);
    cudaGetSymbolAddress((void**)&frames, g_frames);

    init_basis_k<<<(WIN*TCL + 255)/256, 256>>>();
    proj_k<<<BB, CH>>>(param, proj_w, proj_b);

    // layer0: A fused (base + pos)
    gemm3_k<true, true, true ><<<dim3(4, 32), 256>>>(
        (const float*)0, w0, b0, base, pos, act1, NROWS, CH, CH, CH, CH, CH);
    gemm3_k<true, true, false><<<dim3(4, 32), 256>>>(
        act1, w1, b1, (const float*)0, (const float*)0, act0, NROWS, CH, CH, CH, CH, CH);
    gemm3_k<true, true, false><<<dim3(4, 32), 256>>>(
        act0, w2, b2, (const float*)0, (const float*)0, act1, NROWS, CH, CH, CH, CH, CH);
    // out layer: N=514, C stride padded to 544
    gemm3_k<false, true, false><<<dim3(9, 32), 256>>>(
        act1, w_out, b_out, (const float*)0, (const float*)0, xout, NROWS, TC, CH, CH, CH, TCL);

    spec_pre_k <<<(BB*4*NC + 255)/256, 256>>>(noise);
    spec_main_k<<<(BB*4*NC + 255)/256, 256>>>(noise);

    // frames = spec[4096,544] @ basis[512,544]^T  (pads are zero)
    gemm3_k<false, false, false><<<dim3(8, 32), 256>>>(
        spec, basis, (const float*)0, (const float*)0, (const float*)0, frames,
        NROWS, WIN, TCL, TCL, TCL, WIN);

    sig_k<<<(BB*NS + 255)/256, 256>>>();
    extract_k<<<2, 256>>>(times);
    conv_k<<<dim3(NS/1024, BB*NE), 256>>>(out);
}